// round 12
// baseline (speedup 1.0000x reference)
#include <cuda_runtime.h>
#include <cstdint>

// Fixed shapes: B=2, C=128, D=H=W=16
#define NNODE 4096
#define CDIM  128
#define EDIM  46
#define BCNT  2
#define PROJW 192   // theta(64) | phi(64) | G(64)

// ---------------- scratch (device globals) ---------------------------------
__device__ float g_h[BCNT * NNODE * CDIM];
__device__ float g_proj[BCNT * NNODE * PROJW];
__device__ float g_f[BCNT * NNODE * EDIM];
__device__ float g_fp[NNODE * EDIM];
__device__ float g_fpn[NNODE * EDIM];             // relu(l2norm(f_p)) precomputed
__device__ float g_ss[92 * 32];
__device__ float g_ssfp[46 * 32];
__device__ float g_Wcat[PROJW * CDIM];
__device__ float g_bcat[PROJW];
__device__ float g_y[3][BCNT * NNODE * 64];

// line decode: axis0 line=(j,k) step 256; axis1 line=(i,k) step 16; axis2 line=(i,j) step 1
__device__ __forceinline__ void line_decode(int axis, int line,
                                            int& nbase, int& step, int& c0, int& c1) {
    if (axis == 0)      { nbase = line; step = 256; c0 = 0; c1 = 0; }
    else if (axis == 1) { c0 = line >> 4; nbase = (c0 << 8) | (line & 15); step = 16; c1 = 0; }
    else                { c0 = line >> 4; c1 = line & 15; nbase = (c0 << 8) | (c1 << 4); step = 1; }
}
__device__ __forceinline__ int e_pos(int axis, int c0, int c1, int v, int vp) {
    if (axis == 0) return vp < v ? vp : vp + 30;
    if (axis == 1) return c0 + (vp < v ? vp : vp + 15);
    return c0 + c1 + vp;                          // includes self
}

// ---------------- 3xTF32 mma helper ------------------------------------------
__device__ __forceinline__ void mma8(float* c, const uint32_t* a, uint32_t b0, uint32_t b1) {
    asm volatile("mma.sync.aligned.m16n8k8.row.col.f32.tf32.tf32.f32 "
                 "{%0,%1,%2,%3},{%4,%5,%6,%7},{%8,%9},{%0,%1,%2,%3};\n"
                 : "+f"(c[0]), "+f"(c[1]), "+f"(c[2]), "+f"(c[3])
                 : "r"(a[0]), "r"(a[1]), "r"(a[2]), "r"(a[3]), "r"(b0), "r"(b1));
}

// ---------------- K1: prep (transpose + Wcat + bcat + zero ssfp) -------------
__global__ __launch_bounds__(256) void k_prep(
        const float* __restrict__ x,
        const float* __restrict__ Gw, const float* __restrict__ Gb,
        const float* __restrict__ thw, const float* __restrict__ thb,
        const float* __restrict__ phw, const float* __restrict__ phb) {
    __shared__ float tile[32][33];
    const int t = threadIdx.x, bid = blockIdx.x;
    const int gtid = bid * 256 + t, gs = gridDim.x * 256;

    // coalesced transpose via 32x32 smem tiles: 1024 tiles, 2 per block
    for (int task = bid; task < 1024; task += gridDim.x) {
        int b = task >> 9, ct = (task >> 7) & 3, nt = task & 127;
        __syncthreads();
        for (int l = t; l < 1024; l += 256) {
            int cc = l >> 5, nn = l & 31;
            tile[cc][nn] = x[(((b << 7) + (ct << 5) + cc) << 12) + (nt << 5) + nn];
        }
        __syncthreads();
        for (int l = t; l < 1024; l += 256) {
            int cc = l & 31, nn = l >> 5;
            g_h[(((b << 12) + (nt << 5) + nn) << 7) + (ct << 5) + cc] = tile[cc][nn];
        }
    }
    for (int idx = gtid; idx < PROJW * CDIM; idx += gs) {
        int r = idx >> 7, k = idx & 127;
        g_Wcat[idx] = (r < 64) ? thw[r * 128 + k]
                    : (r < 128) ? phw[(r - 64) * 128 + k]
                    : Gw[(r - 128) * 128 + k];
    }
    for (int idx = gtid; idx < PROJW; idx += gs)
        g_bcat[idx] = (idx < 64) ? thb[idx] : (idx < 128) ? phb[idx - 64] : Gb[idx - 128];
    for (int idx = gtid; idx < 46; idx += gs) g_ssfp[idx * 32] = 0.f;
}

// ---------------- K2: gram — ONE line per block, 256 threads -----------------
// mode 0: f_p; geo features computed INLINE (grid 768; no global tensor reads).
// mode 1: f from proj (grid 1536).
// Thread t = (v<<4)|vp computes the single Gram entry (v,vp).
__global__ __launch_bounds__(256, 6) void k_gram(int mode,
        const float* __restrict__ gthw, const float* __restrict__ gthb,
        const float* __restrict__ gphw, const float* __restrict__ gphb) {
    __shared__ float T[2][16][68];                // [theta|phi][node][dim]
    __shared__ float ssl[48];
    int t = threadIdx.x;
    int task = blockIdx.x;
    int b = task / 768, lt = task - b * 768;
    int axis = lt >> 8, line = lt & 255;
    int nbse, st, c0, c1; line_decode(axis, line, nbse, st, c0, c1);

    if (t < 48) ssl[t] = 0.f;

    float* fB; float* ssB;
    if (mode) {
        const float* thB = g_proj + b * NNODE * PROJW;
        fB = g_f + b * NNODE * EDIM; ssB = g_ss + b * EDIM * 32;
        // load 2 tiles x 16 rows x 16 float4: thread t loads theta #t, phi #t
        int r = t >> 4, off = t & 15;
        const float* row = thB + (nbse + r * st) * PROJW + off * 4;
        *(float4*)&T[0][r][off * 4] = *(const float4*)row;        // theta
        *(float4*)&T[1][r][off * 4] = *(const float4*)(row + 64); // phi
    } else {
        fB = g_fp; ssB = g_ssfp;
        // compute geo features inline: node = nbse + r*st; dims off*4..+3
        int r = t >> 4, off = t & 15;
        int n = nbse + r * st;
        int i = n >> 8, j = (n >> 4) & 15, k = n & 15;
        float p0 = i * (1.f / 15.f) - 0.5f;
        float p1 = j * (1.f / 15.f) - 0.5f;
        float p2 = k * (1.f / 15.f) - 0.5f;
#pragma unroll
        for (int q = 0; q < 4; q++) {
            int d = off * 4 + q;
            T[0][r][off * 4 + q] = p0 * gthw[d * 3] + p1 * gthw[d * 3 + 1]
                                 + p2 * gthw[d * 3 + 2] + gthb[d];
            T[1][r][off * 4 + q] = p0 * gphw[d * 3] + p1 * gphw[d * 3 + 1]
                                 + p2 * gphw[d * 3 + 2] + gphb[d];
        }
    }
    __syncthreads();

    int v = t >> 4, vp = t & 15;
    const float4* tr = (const float4*)&T[0][v][0];
    const float4* pr = (const float4*)&T[1][vp][0];
    float acc = 0.f;
#pragma unroll
    for (int d = 0; d < 16; d++) {
        float4 a = tr[d], p = pr[d];
        acc += a.x * p.x + a.y * p.y + a.z * p.z + a.w * p.w;
    }
    if (axis == 2 || v != vp) {
        int e = e_pos(axis, c0, c1, v, vp);
        fB[(nbse + v * st) * EDIM + e] = acc;
        atomicAdd(&ssl[e], acc * acc);
    }
    __syncthreads();
    if (t < 46) {                                 // flush line sums -> global
        float sv = ssl[t];
        if (sv != 0.f) atomicAdd(ssB + t * 32, sv);
    }
}

// ---------------- K3: proj GEMM (3xTF32 mma, 64x64 tile/block, grid 384) -----
// Also zeroes g_ss (block 0) for this round's gram atomics, and on do_fpn
// computes the normalized relu'd f_p table (grid-strided).
__global__ __launch_bounds__(256) void k_proj(int do_fpn) {
    __shared__ float Ah[32][72], Al[32][72], Bh[32][72], Bl[32][72];
    int t = threadIdx.x;
    if (blockIdx.x == 0 && t < 92) g_ss[t * 32] = 0.f;
    if (do_fpn) {
        int gtid = blockIdx.x * 256 + t, gs = gridDim.x * 256;
        for (int idx = gtid; idx < NNODE * EDIM; idx += gs) {
            int e = idx % EDIM;
            g_fpn[idx] = fmaxf(g_fp[idx] / (1e-6f + sqrtf(g_ssfp[e * 32])), 0.f);
        }
    }
    int lane = t & 31, w = t >> 5;
    int g = lane >> 2, tg = lane & 3;
    int mrow = (w & 3) << 4;          // warp m-offset within 64
    int nb = (w >> 2) << 5;           // warp n-offset within 64
    int task = blockIdx.x;
    int rowTile = task / 3;
    int rowBase = rowTile << 6, colBase = (task - rowTile * 3) << 6;
    float acc[4][4];
#pragma unroll
    for (int i = 0; i < 4; i++)
#pragma unroll
        for (int j = 0; j < 4; j++) acc[i][j] = 0.f;

    for (int k0 = 0; k0 < 128; k0 += 32) {
        __syncthreads();
#pragma unroll
        for (int it = 0; it < 2; it++) {
            int idx = t + it * 256;
            int rr = idx & 63, k4 = idx >> 6;
            float4 va = *(const float4*)(g_h + (rowBase + rr) * 128 + k0 + k4 * 4);
            float4 vb = *(const float4*)(g_Wcat + (colBase + rr) * 128 + k0 + k4 * 4);
            const float* vaf = (const float*)&va;
            const float* vbf = (const float*)&vb;
#pragma unroll
            for (int jj = 0; jj < 4; jj++) {
                float av = vaf[jj];
                float ah = __uint_as_float(__float_as_uint(av) & 0xFFFFE000u);
                Ah[k4 * 4 + jj][rr] = ah;
                Al[k4 * 4 + jj][rr] = av - ah;
                float bv = vbf[jj];
                float bh = __uint_as_float(__float_as_uint(bv) & 0xFFFFE000u);
                Bh[k4 * 4 + jj][rr] = bh;
                Bl[k4 * 4 + jj][rr] = bv - bh;
            }
        }
        __syncthreads();
#pragma unroll
        for (int ks = 0; ks < 4; ks++) {
            int kr = ks * 8;
            uint32_t ah[4], al[4];
            ah[0] = __float_as_uint(Ah[kr + tg][mrow + g]);
            ah[1] = __float_as_uint(Ah[kr + tg][mrow + g + 8]);
            ah[2] = __float_as_uint(Ah[kr + tg + 4][mrow + g]);
            ah[3] = __float_as_uint(Ah[kr + tg + 4][mrow + g + 8]);
            al[0] = __float_as_uint(Al[kr + tg][mrow + g]);
            al[1] = __float_as_uint(Al[kr + tg][mrow + g + 8]);
            al[2] = __float_as_uint(Al[kr + tg + 4][mrow + g]);
            al[3] = __float_as_uint(Al[kr + tg + 4][mrow + g + 8]);
#pragma unroll
            for (int ch = 0; ch < 4; ch++) {
                int nn = nb + ch * 8 + g;
                uint32_t bh0 = __float_as_uint(Bh[kr + tg][nn]);
                uint32_t bh1 = __float_as_uint(Bh[kr + tg + 4][nn]);
                uint32_t bl0 = __float_as_uint(Bl[kr + tg][nn]);
                uint32_t bl1 = __float_as_uint(Bl[kr + tg + 4][nn]);
                mma8(acc[ch], ah, bh0, bh1);     // hi*hi
                mma8(acc[ch], ah, bl0, bl1);     // hi*lo
                mma8(acc[ch], al, bh0, bh1);     // lo*hi
            }
        }
    }
#pragma unroll
    for (int ch = 0; ch < 4; ch++) {
        int col = colBase + nb + ch * 8 + 2 * tg;
        int row = rowBase + mrow + g;
        g_proj[row * PROJW + col]           = acc[ch][0] + g_bcat[col];
        g_proj[row * PROJW + col + 1]       = acc[ch][1] + g_bcat[col + 1];
        g_proj[(row + 8) * PROJW + col]     = acc[ch][2] + g_bcat[col];
        g_proj[(row + 8) * PROJW + col + 1] = acc[ch][3] + g_bcat[col + 1];
    }
}

// ---------------- K4: softmax + aggregate (grid 1536, 1 line each) -----------
__global__ __launch_bounds__(256) void k_agg() {
    __shared__ float Gs[16][68];
    __shared__ float fs[16][48];
    __shared__ float nrm2[92];
    int t = threadIdx.x;
    int task = blockIdx.x;
    int b = task / 768, lt = task - b * 768;
    int axis = lt >> 8, line = lt & 255;
    int nb_, st, c0, c1; line_decode(axis, line, nb_, st, c0, c1);

    if (t < 92) nrm2[t] = 1.f / (1e-6f + sqrtf(g_ss[t * 32]));

    int r = t >> 4, c = t & 15;
    // loads into registers (no smem dependency yet)
    float4 gv = *(const float4*)(g_proj + (b * NNODE + nb_ + r * st) * PROJW + 128 + c * 4);
    float fv[3], qv[3]; int lnd[3], le[3];
#pragma unroll
    for (int ii = 0; ii < 3; ii++) {
        int l = t + ii * 256; lnd[ii] = l / 48; le[ii] = l - lnd[ii] * 48;
        if (le[ii] < 46) {
            int n = nb_ + lnd[ii] * st;
            fv[ii] = g_f[(b * NNODE + n) * EDIM + le[ii]];
            qv[ii] = g_fpn[n * EDIM + le[ii]];
        }
    }
    __syncthreads();                              // nrm2 visible
    *(float4*)&Gs[r][c * 4] = gv;
#pragma unroll
    for (int ii = 0; ii < 3; ii++)
        fs[lnd[ii]][le[ii]] = (le[ii] < 46)
            ? fv[ii] * nrm2[b * 46 + le[ii]] + qv[ii] : -1e30f;
    __syncthreads();

    int ty = r, tx = c;
    float a0 = fs[ty][tx], a1 = fs[ty][tx + 16], a2 = fs[ty][tx + 32];
    float m = fmaxf(a0, fmaxf(a1, a2));
#pragma unroll
    for (int o = 8; o; o >>= 1) m = fmaxf(m, __shfl_xor_sync(0xffffffffu, m, o));
    float e0 = expf(a0 - m), e1 = expf(a1 - m), e2 = expf(a2 - m);
    float z = e0 + e1 + e2;
#pragma unroll
    for (int o = 8; o; o >>= 1) z += __shfl_xor_sync(0xffffffffu, z, o);
    float invZ = 1.f / z;
    fs[ty][tx] = e0; fs[ty][tx + 16] = e1; fs[ty][tx + 32] = e2;
    __syncwarp();

    float4 acc = {0.f, 0.f, 0.f, 0.f};
#pragma unroll
    for (int vp = 0; vp < 16; vp++) {
        float w;
        if (axis == 2)      w = fs[ty][c0 + c1 + vp];
        else if (vp == ty)  w = 0.f;
        else if (axis == 0) w = fs[ty][vp < ty ? vp : vp + 30];
        else                w = fs[ty][c0 + (vp < ty ? vp : vp + 15)];
        float4 gg = *(const float4*)&Gs[vp][tx * 4];
        acc.x += w * gg.x; acc.y += w * gg.y; acc.z += w * gg.z; acc.w += w * gg.w;
    }
    acc.x *= invZ; acc.y *= invZ; acc.z *= invZ; acc.w *= invZ;
    int n = nb_ + ty * st;
    *(float4*)&g_y[axis][(b * NNODE + n) * 64 + tx * 4] = acc;
}

// ---------------- K5: residual GEMM (grid 256, 64x64 tile) -------------------
__global__ __launch_bounds__(256) void k_resid(const float* __restrict__ rw,
                                               const float* __restrict__ rb,
                                               float* __restrict__ outp, int last) {
    __shared__ float A[32][68], B[32][68];
    int task = blockIdx.x;
    int rowBase = (task >> 1) << 6, colBase = (task & 1) << 6;
    int t = threadIdx.x, tx = t & 15, ty = t >> 4;
    const int AX = BCNT * NNODE * 64;
    float acc[4][4] = {};
    for (int k0 = 0; k0 < 64; k0 += 32) {
#pragma unroll
        for (int it = 0; it < 2; it++) {
            int idx = t + it * 256;
            int r = idx & 63, k4 = idx >> 6;
            const float* yb = &g_y[0][(rowBase + r) * 64 + k0 + k4 * 4];
            float4 v0 = *(const float4*)yb;
            float4 v1 = *(const float4*)(yb + AX);
            float4 v2 = *(const float4*)(yb + 2 * AX);
            A[k4 * 4 + 0][r] = v0.x + v1.x + v2.x;
            A[k4 * 4 + 1][r] = v0.y + v1.y + v2.y;
            A[k4 * 4 + 2][r] = v0.z + v1.z + v2.z;
            A[k4 * 4 + 3][r] = v0.w + v1.w + v2.w;
            float4 w = *(const float4*)(rw + (colBase + r) * 64 + k0 + k4 * 4);
            B[k4 * 4 + 0][r] = w.x; B[k4 * 4 + 1][r] = w.y;
            B[k4 * 4 + 2][r] = w.z; B[k4 * 4 + 3][r] = w.w;
        }
        __syncthreads();
#pragma unroll
        for (int kk = 0; kk < 32; kk++) {
            float4 a = *(const float4*)&A[kk][ty * 4];
            float4 b = *(const float4*)&B[kk][tx * 4];
            float av[4] = {a.x, a.y, a.z, a.w};
            float bv[4] = {b.x, b.y, b.z, b.w};
#pragma unroll
            for (int i = 0; i < 4; i++)
#pragma unroll
                for (int j = 0; j < 4; j++) acc[i][j] += av[i] * bv[j];
        }
        __syncthreads();
    }
#pragma unroll
    for (int i = 0; i < 4; i++) {
        int row = rowBase + ty * 4 + i;
#pragma unroll
        for (int j = 0; j < 4; j++) {
            int c = colBase + tx * 4 + j;
            float val = acc[i][j] + rb[c] + g_h[row * 128 + c];
            if (last) {
                int b = row >> 12, n = row & 4095;
                outp[(((b << 7) + c) << 12) + n] = val;
            } else {
                g_h[row * 128 + c] = val;
            }
        }
    }
}

// ---------------------------------------------------------------------------
extern "C" void kernel_launch(void* const* d_in, const int* in_sizes, int n_in,
                              void* d_out, int out_size) {
    const float* x    = (const float*)d_in[0];
    const float* G_w  = (const float*)d_in[1];
    const float* G_b  = (const float*)d_in[2];
    const float* th_w = (const float*)d_in[3];
    const float* th_b = (const float*)d_in[4];
    const float* ph_w = (const float*)d_in[5];
    const float* ph_b = (const float*)d_in[6];
    const float* r_w  = (const float*)d_in[7];
    const float* r_b  = (const float*)d_in[8];
    const float* gt_w = (const float*)d_in[9];
    const float* gt_b = (const float*)d_in[10];
    const float* gp_w = (const float*)d_in[11];
    const float* gp_b = (const float*)d_in[12];
    float* out = (float*)d_out;

    k_prep<<<512, 256>>>(x, G_w, G_b, th_w, th_b, ph_w, ph_b);
    k_gram<<<768, 256>>>(0, gt_w, gt_b, gp_w, gp_b);   // f_p lines, geo inline

    for (int r = 0; r < 3; r++) {
        k_proj<<<384, 256>>>(r == 0 ? 1 : 0);          // + zero g_ss, + FPN on r0
        k_gram<<<1536, 256>>>(1, gt_w, gt_b, gp_w, gp_b); // f lines
        k_agg<<<1536, 256>>>();
        k_resid<<<256, 256>>>(r_w, r_b, out, r == 2);
    }
}

// round 13
// speedup vs baseline: 1.0478x; 1.0478x over previous
#include <cuda_runtime.h>
#include <cstdint>

// Fixed shapes: B=2, C=128, D=H=W=16
#define NNODE 4096
#define CDIM  128
#define EDIM  46
#define BCNT  2
#define PROJW 192   // theta(64) | phi(64) | G(64)

// ---------------- scratch (device globals) ---------------------------------
__device__ float g_h[BCNT * NNODE * CDIM];
__device__ float g_proj[BCNT * NNODE * PROJW];
__device__ float g_f[BCNT * NNODE * EDIM];
__device__ float g_fp[NNODE * EDIM];
__device__ float g_fpn[NNODE * EDIM];             // relu(l2norm(f_p)) precomputed
__device__ float g_pth[NNODE * 64];
__device__ float g_pph[NNODE * 64];
__device__ float g_ss[92 * 32];
__device__ float g_ssfp[46 * 32];
__device__ float g_Wcat[PROJW * CDIM];
__device__ float g_bcat[PROJW];
__device__ float g_y[3][BCNT * NNODE * 64];

// line decode: axis0 line=(j,k) step 256; axis1 line=(i,k) step 16; axis2 line=(i,j) step 1
__device__ __forceinline__ void line_decode(int axis, int line,
                                            int& nbase, int& step, int& c0, int& c1) {
    if (axis == 0)      { nbase = line; step = 256; c0 = 0; c1 = 0; }
    else if (axis == 1) { c0 = line >> 4; nbase = (c0 << 8) | (line & 15); step = 16; c1 = 0; }
    else                { c0 = line >> 4; c1 = line & 15; nbase = (c0 << 8) | (c1 << 4); step = 1; }
}
__device__ __forceinline__ int e_pos(int axis, int c0, int c1, int v, int vp) {
    if (axis == 0) return vp < v ? vp : vp + 30;
    if (axis == 1) return c0 + (vp < v ? vp : vp + 15);
    return c0 + c1 + vp;                          // includes self
}

// ---------------- 3xTF32 mma helper ------------------------------------------
__device__ __forceinline__ void mma8(float* c, const uint32_t* a, uint32_t b0, uint32_t b1) {
    asm volatile("mma.sync.aligned.m16n8k8.row.col.f32.tf32.tf32.f32 "
                 "{%0,%1,%2,%3},{%4,%5,%6,%7},{%8,%9},{%0,%1,%2,%3};\n"
                 : "+f"(c[0]), "+f"(c[1]), "+f"(c[2]), "+f"(c[3])
                 : "r"(a[0]), "r"(a[1]), "r"(a[2]), "r"(a[3]), "r"(b0), "r"(b1));
}

// ---------------- shared proj tile body (64 rows x 64 cols, 3xTF32) ----------
struct ProjSmem { float Ah[32][72], Al[32][72], Bh[32][72], Bl[32][72]; };

__device__ __forceinline__ void proj_tile_body(ProjSmem& ps, int rowBase, int colBase) {
    int t = threadIdx.x;
    int lane = t & 31, w = t >> 5;
    int g = lane >> 2, tg = lane & 3;
    int mrow = (w & 3) << 4;          // warp m-offset within 64
    int nb = (w >> 2) << 5;           // warp n-offset within 64
    float acc[4][4];
#pragma unroll
    for (int i = 0; i < 4; i++)
#pragma unroll
        for (int j = 0; j < 4; j++) acc[i][j] = 0.f;

    for (int k0 = 0; k0 < 128; k0 += 32) {
        __syncthreads();
#pragma unroll
        for (int it = 0; it < 2; it++) {
            int idx = t + it * 256;
            int rr = idx & 63, k4 = idx >> 6;
            float4 va = *(const float4*)(g_h + (rowBase + rr) * 128 + k0 + k4 * 4);
            float4 vb = *(const float4*)(g_Wcat + (colBase + rr) * 128 + k0 + k4 * 4);
            const float* vaf = (const float*)&va;
            const float* vbf = (const float*)&vb;
#pragma unroll
            for (int jj = 0; jj < 4; jj++) {
                float av = vaf[jj];
                float ah = __uint_as_float(__float_as_uint(av) & 0xFFFFE000u);
                ps.Ah[k4 * 4 + jj][rr] = ah;
                ps.Al[k4 * 4 + jj][rr] = av - ah;
                float bv = vbf[jj];
                float bh = __uint_as_float(__float_as_uint(bv) & 0xFFFFE000u);
                ps.Bh[k4 * 4 + jj][rr] = bh;
                ps.Bl[k4 * 4 + jj][rr] = bv - bh;
            }
        }
        __syncthreads();
#pragma unroll
        for (int ks = 0; ks < 4; ks++) {
            int kr = ks * 8;
            uint32_t ah[4], al[4];
            ah[0] = __float_as_uint(ps.Ah[kr + tg][mrow + g]);
            ah[1] = __float_as_uint(ps.Ah[kr + tg][mrow + g + 8]);
            ah[2] = __float_as_uint(ps.Ah[kr + tg + 4][mrow + g]);
            ah[3] = __float_as_uint(ps.Ah[kr + tg + 4][mrow + g + 8]);
            al[0] = __float_as_uint(ps.Al[kr + tg][mrow + g]);
            al[1] = __float_as_uint(ps.Al[kr + tg][mrow + g + 8]);
            al[2] = __float_as_uint(ps.Al[kr + tg + 4][mrow + g]);
            al[3] = __float_as_uint(ps.Al[kr + tg + 4][mrow + g + 8]);
#pragma unroll
            for (int ch = 0; ch < 4; ch++) {
                int nn = nb + ch * 8 + g;
                uint32_t bh0 = __float_as_uint(ps.Bh[kr + tg][nn]);
                uint32_t bh1 = __float_as_uint(ps.Bh[kr + tg + 4][nn]);
                uint32_t bl0 = __float_as_uint(ps.Bl[kr + tg][nn]);
                uint32_t bl1 = __float_as_uint(ps.Bl[kr + tg + 4][nn]);
                mma8(acc[ch], ah, bh0, bh1);     // hi*hi
                mma8(acc[ch], ah, bl0, bl1);     // hi*lo
                mma8(acc[ch], al, bh0, bh1);     // lo*hi
            }
        }
    }
#pragma unroll
    for (int ch = 0; ch < 4; ch++) {
        int col = colBase + nb + ch * 8 + 2 * tg;
        int row = rowBase + mrow + g;
        g_proj[row * PROJW + col]           = acc[ch][0] + g_bcat[col];
        g_proj[row * PROJW + col + 1]       = acc[ch][1] + g_bcat[col + 1];
        g_proj[(row + 8) * PROJW + col]     = acc[ch][2] + g_bcat[col];
        g_proj[(row + 8) * PROJW + col + 1] = acc[ch][3] + g_bcat[col + 1];
    }
    __syncthreads();
}

// ---------------- K1: prep (transpose + Wcat + bcat + geo + zero ssfp) -------
__global__ __launch_bounds__(256) void k_prep(
        const float* __restrict__ x,
        const float* __restrict__ Gw, const float* __restrict__ Gb,
        const float* __restrict__ thw, const float* __restrict__ thb,
        const float* __restrict__ phw, const float* __restrict__ phb,
        const float* __restrict__ gthw, const float* __restrict__ gthb,
        const float* __restrict__ gphw, const float* __restrict__ gphb) {
    __shared__ float tile[32][33];
    const int t = threadIdx.x, bid = blockIdx.x;
    const int gtid = bid * 256 + t, gs = gridDim.x * 256;

    for (int task = bid; task < 1024; task += gridDim.x) {
        int b = task >> 9, ct = (task >> 7) & 3, nt = task & 127;
        __syncthreads();
        for (int l = t; l < 1024; l += 256) {
            int cc = l >> 5, nn = l & 31;
            tile[cc][nn] = x[(((b << 7) + (ct << 5) + cc) << 12) + (nt << 5) + nn];
        }
        __syncthreads();
        for (int l = t; l < 1024; l += 256) {
            int cc = l & 31, nn = l >> 5;
            g_h[(((b << 12) + (nt << 5) + nn) << 7) + (ct << 5) + cc] = tile[cc][nn];
        }
    }
    for (int idx = gtid; idx < PROJW * CDIM; idx += gs) {
        int r = idx >> 7, k = idx & 127;
        g_Wcat[idx] = (r < 64) ? thw[r * 128 + k]
                    : (r < 128) ? phw[(r - 64) * 128 + k]
                    : Gw[(r - 128) * 128 + k];
    }
    for (int idx = gtid; idx < PROJW; idx += gs)
        g_bcat[idx] = (idx < 64) ? thb[idx] : (idx < 128) ? phb[idx - 64] : Gb[idx - 128];
    for (int idx = gtid; idx < 46; idx += gs) g_ssfp[idx * 32] = 0.f;
    for (int idx = gtid; idx < NNODE * 64; idx += gs) {
        int n = idx >> 6, d = idx & 63;
        int i = n >> 8, j = (n >> 4) & 15, k = n & 15;
        float p0 = i * (1.f / 15.f) - 0.5f;
        float p1 = j * (1.f / 15.f) - 0.5f;
        float p2 = k * (1.f / 15.f) - 0.5f;
        g_pth[idx] = p0 * gthw[d * 3] + p1 * gthw[d * 3 + 1] + p2 * gthw[d * 3 + 2] + gthb[d];
        g_pph[idx] = p0 * gphw[d * 3] + p1 * gphw[d * 3 + 1] + p2 * gphw[d * 3 + 2] + gphb[d];
    }
}

// ---------------- K2: gram — ONE line per block, 64 threads (R11 champion) ---
__global__ __launch_bounds__(64) void k_gram(int mode) {
    __shared__ float T[2][16][68];                // [theta|phi][node][dim]
    __shared__ float ssl[48];
    int t = threadIdx.x;
    int task = blockIdx.x;
    int b = task / 768, lt = task - b * 768;
    int axis = lt >> 8, line = lt & 255;

    const float* thB; const float* phB; int stride; float* fB; float* ssB;
    if (mode) {
        thB = g_proj + b * NNODE * PROJW; phB = thB + 64; stride = PROJW;
        fB = g_f + b * NNODE * EDIM; ssB = g_ss + b * EDIM * 32;
    } else {
        thB = g_pth; phB = g_pph; stride = 64;
        fB = g_fp; ssB = g_ssfp;
    }

    if (t < 48) ssl[t] = 0.f;

    int nbse, st, c0, c1; line_decode(axis, line, nbse, st, c0, c1);

#pragma unroll
    for (int i = 0; i < 8; i++) {
        int c = t + (i << 6);                     // 0..511
        int which = c >> 8;
        int r = (c >> 4) & 15, off = c & 15;
        const float* src = (which ? phB : thB) + (nbse + r * st) * stride + off * 4;
        *(float4*)&T[which][r][off * 4] = *(const float4*)src;
    }
    __syncthreads();

    int v2 = t >> 3, vp2 = t & 7;
    const float4* t0 = (const float4*)&T[0][2 * v2][0];
    const float4* t1 = (const float4*)&T[0][2 * v2 + 1][0];
    const float4* p0 = (const float4*)&T[1][2 * vp2][0];
    const float4* p1 = (const float4*)&T[1][2 * vp2 + 1][0];
    float a00 = 0.f, a01 = 0.f, a10 = 0.f, a11 = 0.f;   // 4 independent chains
#pragma unroll
    for (int d = 0; d < 16; d++) {
        float4 x0 = t0[d], x1 = t1[d], y0 = p0[d], y1 = p1[d];
        a00 += x0.x * y0.x + x0.y * y0.y + x0.z * y0.z + x0.w * y0.w;
        a01 += x0.x * y1.x + x0.y * y1.y + x0.z * y1.z + x0.w * y1.w;
        a10 += x1.x * y0.x + x1.y * y0.y + x1.z * y0.z + x1.w * y0.w;
        a11 += x1.x * y1.x + x1.y * y1.y + x1.z * y1.z + x1.w * y1.w;
    }
    float accs[2][2] = {{a00, a01}, {a10, a11}};
#pragma unroll
    for (int iv = 0; iv < 2; iv++)
#pragma unroll
        for (int jv = 0; jv < 2; jv++) {
            int v = 2 * v2 + iv, vp = 2 * vp2 + jv;
            float a = accs[iv][jv];
            if (axis == 2 || v != vp) {
                int e = e_pos(axis, c0, c1, v, vp);
                fB[(nbse + v * st) * EDIM + e] = a;
                atomicAdd(&ssl[e], a * a);
            }
        }
    __syncthreads();
    if (t < 46) {
        float sv = ssl[t];
        if (sv != 0.f) atomicAdd(ssB + t * 32, sv);
    }
}

// ---------------- K3: round-0 proj (grid 384) + zero g_ss + FPN --------------
__global__ __launch_bounds__(256) void k_proj(int do_fpn) {
    __shared__ ProjSmem ps;
    int t = threadIdx.x;
    if (blockIdx.x == 0 && t < 92) g_ss[t * 32] = 0.f;
    if (do_fpn) {
        int gtid = blockIdx.x * 256 + t, gs = gridDim.x * 256;
        for (int idx = gtid; idx < NNODE * EDIM; idx += gs) {
            int e = idx % EDIM;
            g_fpn[idx] = fmaxf(g_fp[idx] / (1e-6f + sqrtf(g_ssfp[e * 32])), 0.f);
        }
    }
    int task = blockIdx.x;
    int rowTile = task / 3;
    proj_tile_body(ps, rowTile << 6, (task - rowTile * 3) << 6);
}

// ---------------- K3b: fused resid(prev round) + proj (grid 128) -------------
// Block owns 64 h-rows: computes h += (y0+y1+y2)@rw^T + rb for its rows,
// stores g_h, then runs all 3 proj col-tiles for the same rows.
struct ResSmem { float A[32][68]; float B[32][132]; };
union __align__(16) PRSmem { ResSmem r; ProjSmem p; };

__global__ __launch_bounds__(256) void k_projres(const float* __restrict__ rw,
                                                 const float* __restrict__ rb) {
    __shared__ PRSmem sm;
    int t = threadIdx.x;
    if (blockIdx.x == 0 && t < 92) g_ss[t * 32] = 0.f;
    int rowBase = blockIdx.x << 6;
    int tx = t & 15, ty = t >> 4;
    const int AX = BCNT * NNODE * 64;

    // ---- resid: acc[4][8] = rows 4ty..+3, cols 8tx..+7 of delta[64][128] ----
    float acc[4][8];
#pragma unroll
    for (int i = 0; i < 4; i++)
#pragma unroll
        for (int j = 0; j < 8; j++) acc[i][j] = 0.f;

    for (int k0 = 0; k0 < 64; k0 += 32) {
        // A: y-sum [32 k][64 rows]
#pragma unroll
        for (int it = 0; it < 2; it++) {
            int idx = t + it * 256;
            int r = idx & 63, k4 = idx >> 6;
            const float* yb = &g_y[0][(rowBase + r) * 64 + k0 + k4 * 4];
            float4 v0 = *(const float4*)yb;
            float4 v1 = *(const float4*)(yb + AX);
            float4 v2 = *(const float4*)(yb + 2 * AX);
            sm.r.A[k4 * 4 + 0][r] = v0.x + v1.x + v2.x;
            sm.r.A[k4 * 4 + 1][r] = v0.y + v1.y + v2.y;
            sm.r.A[k4 * 4 + 2][r] = v0.z + v1.z + v2.z;
            sm.r.A[k4 * 4 + 3][r] = v0.w + v1.w + v2.w;
        }
        // B: rw [32 k][128 cols]
#pragma unroll
        for (int it = 0; it < 4; it++) {
            int idx = t + it * 256;
            int cc = idx & 127, k4 = idx >> 7;
            float4 w = *(const float4*)(rw + cc * 64 + k0 + k4 * 4);
            sm.r.B[k4 * 4 + 0][cc] = w.x; sm.r.B[k4 * 4 + 1][cc] = w.y;
            sm.r.B[k4 * 4 + 2][cc] = w.z; sm.r.B[k4 * 4 + 3][cc] = w.w;
        }
        __syncthreads();
#pragma unroll
        for (int kk = 0; kk < 32; kk++) {
            float4 a = *(const float4*)&sm.r.A[kk][ty * 4];
            float4 b0 = *(const float4*)&sm.r.B[kk][tx * 8];
            float4 b1 = *(const float4*)&sm.r.B[kk][tx * 8 + 4];
            float av[4] = {a.x, a.y, a.z, a.w};
            float bv[8] = {b0.x, b0.y, b0.z, b0.w, b1.x, b1.y, b1.z, b1.w};
#pragma unroll
            for (int i = 0; i < 4; i++)
#pragma unroll
                for (int j = 0; j < 8; j++) acc[i][j] += av[i] * bv[j];
        }
        __syncthreads();
    }
    // h_new = h + delta + rb -> g_h
#pragma unroll
    for (int i = 0; i < 4; i++) {
        int row = rowBase + ty * 4 + i;
        float* hp = &g_h[row * 128 + tx * 8];
        float4 h0 = *(const float4*)hp;
        float4 h1 = *(const float4*)(hp + 4);
        const float* rbp = rb + tx * 8;
        float4 o0, o1;
        o0.x = h0.x + acc[i][0] + rbp[0]; o0.y = h0.y + acc[i][1] + rbp[1];
        o0.z = h0.z + acc[i][2] + rbp[2]; o0.w = h0.w + acc[i][3] + rbp[3];
        o1.x = h1.x + acc[i][4] + rbp[4]; o1.y = h1.y + acc[i][5] + rbp[5];
        o1.z = h1.z + acc[i][6] + rbp[6]; o1.w = h1.w + acc[i][7] + rbp[7];
        *(float4*)hp = o0;
        *(float4*)(hp + 4) = o1;
    }
    __threadfence_block();
    __syncthreads();

    // ---- proj: 3 col tiles over the same 64 rows (reads updated g_h) -------
    for (int ct = 0; ct < 3; ct++)
        proj_tile_body(sm.p, rowBase, ct << 6);
}

// ---------------- K4: softmax + aggregate (grid 1536, 1 line each) -----------
__global__ __launch_bounds__(256) void k_agg() {
    __shared__ float Gs[16][68];
    __shared__ float fs[16][48];
    __shared__ float nrm2[92];
    int t = threadIdx.x;
    int task = blockIdx.x;
    int b = task / 768, lt = task - b * 768;
    int axis = lt >> 8, line = lt & 255;
    int nb_, st, c0, c1; line_decode(axis, line, nb_, st, c0, c1);

    if (t < 92) nrm2[t] = 1.f / (1e-6f + sqrtf(g_ss[t * 32]));

    int r = t >> 4, c = t & 15;
    float4 gv = *(const float4*)(g_proj + (b * NNODE + nb_ + r * st) * PROJW + 128 + c * 4);
    float fv[3], qv[3]; int lnd[3], le[3];
#pragma unroll
    for (int ii = 0; ii < 3; ii++) {
        int l = t + ii * 256; lnd[ii] = l / 48; le[ii] = l - lnd[ii] * 48;
        if (le[ii] < 46) {
            int n = nb_ + lnd[ii] * st;
            fv[ii] = g_f[(b * NNODE + n) * EDIM + le[ii]];
            qv[ii] = g_fpn[n * EDIM + le[ii]];
        }
    }
    __syncthreads();
    *(float4*)&Gs[r][c * 4] = gv;
#pragma unroll
    for (int ii = 0; ii < 3; ii++)
        fs[lnd[ii]][le[ii]] = (le[ii] < 46)
            ? fv[ii] * nrm2[b * 46 + le[ii]] + qv[ii] : -1e30f;
    __syncthreads();

    int ty = r, tx = c;
    float a0 = fs[ty][tx], a1 = fs[ty][tx + 16], a2 = fs[ty][tx + 32];
    float m = fmaxf(a0, fmaxf(a1, a2));
#pragma unroll
    for (int o = 8; o; o >>= 1) m = fmaxf(m, __shfl_xor_sync(0xffffffffu, m, o));
    float e0 = expf(a0 - m), e1 = expf(a1 - m), e2 = expf(a2 - m);
    float z = e0 + e1 + e2;
#pragma unroll
    for (int o = 8; o; o >>= 1) z += __shfl_xor_sync(0xffffffffu, z, o);
    float invZ = 1.f / z;
    fs[ty][tx] = e0; fs[ty][tx + 16] = e1; fs[ty][tx + 32] = e2;
    __syncwarp();

    float4 acc = {0.f, 0.f, 0.f, 0.f};
#pragma unroll
    for (int vp = 0; vp < 16; vp++) {
        float w;
        if (axis == 2)      w = fs[ty][c0 + c1 + vp];
        else if (vp == ty)  w = 0.f;
        else if (axis == 0) w = fs[ty][vp < ty ? vp : vp + 30];
        else                w = fs[ty][c0 + (vp < ty ? vp : vp + 15)];
        float4 gg = *(const float4*)&Gs[vp][tx * 4];
        acc.x += w * gg.x; acc.y += w * gg.y; acc.z += w * gg.z; acc.w += w * gg.w;
    }
    acc.x *= invZ; acc.y *= invZ; acc.z *= invZ; acc.w *= invZ;
    int n = nb_ + ty * st;
    *(float4*)&g_y[axis][(b * NNODE + n) * 64 + tx * 4] = acc;
}

// ---------------- K5: final residual GEMM -> out (grid 256) ------------------
__global__ __launch_bounds__(256) void k_resid(const float* __restrict__ rw,
                                               const float* __restrict__ rb,
                                               float* __restrict__ outp) {
    __shared__ float A[32][68], B[32][68];
    int task = blockIdx.x;
    int rowBase = (task >> 1) << 6, colBase = (task & 1) << 6;
    int t = threadIdx.x, tx = t & 15, ty = t >> 4;
    const int AX = BCNT * NNODE * 64;
    float acc[4][4] = {};
    for (int k0 = 0; k0 < 64; k0 += 32) {
#pragma unroll
        for (int it = 0; it < 2; it++) {
            int idx = t + it * 256;
            int r = idx & 63, k4 = idx >> 6;
            const float* yb = &g_y[0][(rowBase + r) * 64 + k0 + k4 * 4];
            float4 v0 = *(const float4*)yb;
            float4 v1 = *(const float4*)(yb + AX);
            float4 v2 = *(const float4*)(yb + 2 * AX);
            A[k4 * 4 + 0][r] = v0.x + v1.x + v2.x;
            A[k4 * 4 + 1][r] = v0.y + v1.y + v2.y;
            A[k4 * 4 + 2][r] = v0.z + v1.z + v2.z;
            A[k4 * 4 + 3][r] = v0.w + v1.w + v2.w;
            float4 w = *(const float4*)(rw + (colBase + r) * 64 + k0 + k4 * 4);
            B[k4 * 4 + 0][r] = w.x; B[k4 * 4 + 1][r] = w.y;
            B[k4 * 4 + 2][r] = w.z; B[k4 * 4 + 3][r] = w.w;
        }
        __syncthreads();
#pragma unroll
        for (int kk = 0; kk < 32; kk++) {
            float4 a = *(const float4*)&A[kk][ty * 4];
            float4 b = *(const float4*)&B[kk][tx * 4];
            float av[4] = {a.x, a.y, a.z, a.w};
            float bv[4] = {b.x, b.y, b.z, b.w};
#pragma unroll
            for (int i = 0; i < 4; i++)
#pragma unroll
                for (int j = 0; j < 4; j++) acc[i][j] += av[i] * bv[j];
        }
        __syncthreads();
    }
#pragma unroll
    for (int i = 0; i < 4; i++) {
        int row = rowBase + ty * 4 + i;
#pragma unroll
        for (int j = 0; j < 4; j++) {
            int c = colBase + tx * 4 + j;
            float val = acc[i][j] + rb[c] + g_h[row * 128 + c];
            int b = row >> 12, n = row & 4095;
            outp[(((b << 7) + c) << 12) + n] = val;
        }
    }
}

// ---------------------------------------------------------------------------
extern "C" void kernel_launch(void* const* d_in, const int* in_sizes, int n_in,
                              void* d_out, int out_size) {
    const float* x    = (const float*)d_in[0];
    const float* G_w  = (const float*)d_in[1];
    const float* G_b  = (const float*)d_in[2];
    const float* th_w = (const float*)d_in[3];
    const float* th_b = (const float*)d_in[4];
    const float* ph_w = (const float*)d_in[5];
    const float* ph_b = (const float*)d_in[6];
    const float* r_w  = (const float*)d_in[7];
    const float* r_b  = (const float*)d_in[8];
    const float* gt_w = (const float*)d_in[9];
    const float* gt_b = (const float*)d_in[10];
    const float* gp_w = (const float*)d_in[11];
    const float* gp_b = (const float*)d_in[12];
    float* out = (float*)d_out;

    k_prep<<<512, 256>>>(x, G_w, G_b, th_w, th_b, ph_w, ph_b,
                         gt_w, gt_b, gp_w, gp_b);
    k_gram<<<768, 64>>>(0);                        // f_p lines

    // round 0
    k_proj<<<384, 256>>>(1);                       // + zero g_ss, + FPN
    k_gram<<<1536, 64>>>(1);
    k_agg<<<1536, 256>>>();

    // rounds 1,2: resid of previous round fused into proj
    for (int r = 1; r < 3; r++) {
        k_projres<<<128, 256>>>(r_w, r_b);         // + zero g_ss
        k_gram<<<1536, 64>>>(1);
        k_agg<<<1536, 256>>>();
    }

    k_resid<<<256, 256>>>(r_w, r_b, out);          // final -> out
}